// round 16
// baseline (speedup 1.0000x reference)
#include <cuda_runtime.h>
#include <cuda_bf16.h>
#include <cstdint>
#include <cstddef>

// ---------------------------------------------------------------------------
// Problem constants
// ---------------------------------------------------------------------------
#define S_LEN 16384
#define D_HID 1280
#define H_NUM 16
#define HD_DIM 80
#define WS_WIN 64
#define NW_WIN (S_LEN / WS_WIN)   // 256
#define QKV_N (3 * D_HID)         // 3840
#define KDIM 1280

// GEMM tiling: CTA 128x128, BK=32 fp32, 8 warps (2Mx4N), warp tile 64x32.
#define BM 128
#define BN 128
#define BK 32
#define STAGES 3
#define KT_ITERS (KDIM / BK)      // 40
#define STAGE_BYTES 32768         // A 16K | B 16K
#define GEMM_SMEM (STAGES * STAGE_BYTES)   // 98304

// ---------------------------------------------------------------------------
// Scratch (device globals: allocation-free contract)
// ---------------------------------------------------------------------------
__device__ float g_qkv[(size_t)S_LEN * QKV_N];     // fp32 qkv output
__device__ float g_hid_t[(size_t)S_LEN * D_HID];   // tf32-rounded hidden
__device__ float g_wqkv_t[(size_t)QKV_N * D_HID];  // tf32-rounded qkv weight
__device__ float g_wproj_t[(size_t)D_HID * D_HID]; // tf32-rounded proj weight
__device__ float g_attn_t[(size_t)S_LEN * D_HID];  // tf32-rounded attn output

// ---------------------------------------------------------------------------
// PTX helpers (baseline sm_80+ only -- harness targets plain sm_100)
// ---------------------------------------------------------------------------
__device__ __forceinline__ uint32_t smem_u32(const void* p) {
    uint32_t a;
    asm("{ .reg .u64 t; cvta.to.shared.u64 t, %1; cvt.u32.u64 %0, t; }"
        : "=r"(a) : "l"(p));
    return a;
}

__device__ __forceinline__ float to_tf32f(float x) {
    uint32_t v;
    asm("cvt.rna.tf32.f32 %0, %1;" : "=r"(v) : "f"(x));
    return __uint_as_float(v);
}

// split fp32 bits into tf32 hi + tf32 lo (x = hi + lo + O(2^-24))
__device__ __forceinline__ void split_tf32(uint32_t x, uint32_t& h, uint32_t& l) {
    const float xf = __uint_as_float(x);
    uint32_t hb;
    asm("cvt.rna.tf32.f32 %0, %1;" : "=r"(hb) : "f"(xf));
    const float r = xf - __uint_as_float(hb);
    asm("cvt.rna.tf32.f32 %0, %1;" : "=r"(l) : "f"(r));
    h = hb;
}

#define CP_ASYNC16(smem_addr, gptr) \
    asm volatile("cp.async.cg.shared.global [%0], [%1], 16;\n" \
                 :: "r"(smem_addr), "l"(gptr))
#define CP_ASYNC_COMMIT() asm volatile("cp.async.commit_group;\n" ::: "memory")
#define CP_ASYNC_WAIT1()  asm volatile("cp.async.wait_group 1;\n" ::: "memory")

#define LDSM_X4(r0, r1, r2, r3, addr) \
    asm volatile("ldmatrix.sync.aligned.m8n8.x4.shared.b16 {%0,%1,%2,%3}, [%4];" \
                 : "=r"(r0), "=r"(r1), "=r"(r2), "=r"(r3) : "r"(addr))

#define MMA_TF32(d, a0, a1, a2, a3, b0, b1) \
    asm volatile("mma.sync.aligned.m16n8k8.row.col.f32.tf32.tf32.f32 " \
                 "{%0,%1,%2,%3}, {%4,%5,%6,%7}, {%8,%9}, {%0,%1,%2,%3};" \
                 : "+f"((d)[0]), "+f"((d)[1]), "+f"((d)[2]), "+f"((d)[3]) \
                 : "r"(a0), "r"(a1), "r"(a2), "r"(a3), "r"(b0), "r"(b1))

// ---------------------------------------------------------------------------
// tf32 mma.sync GEMM: cp.async issues spread through the k8 loop (2 per k8)
// ---------------------------------------------------------------------------
__global__ void __launch_bounds__(256, 2) gemm_tf32(
    const float* __restrict__ A, const float* __restrict__ B,
    const float* __restrict__ bias, float* __restrict__ C, int Ntot)
{
    extern __shared__ char smem[];
    const uint32_t sb = smem_u32(smem);
    const int tid = threadIdx.x;
    const int wid = tid >> 5, lane = tid & 31;
    const int warp_m = wid & 1;
    const int warp_n = wid >> 1;
    const int m0 = blockIdx.y * BM;
    const int n0 = blockIdx.x * BN;

    const float* gptr[8];
    uint32_t soff[8];
    #pragma unroll
    for (int t = 0; t < 8; t++) {
        const int idx = tid + t * 256;
        int row, c;
        uint32_t mbase;
        const float* base;
        int r0;
        if (idx < 1024) {
            row = idx >> 3; c = idx & 7;
            base = A; mbase = 0; r0 = m0 + row;
        } else {
            const int j = idx - 1024;
            row = j >> 3; c = j & 7;
            base = B; mbase = 16384; r0 = n0 + row;
        }
        gptr[t] = base + (size_t)r0 * KDIM + c * 4;
        soff[t] = mbase + (uint32_t)(row * 128 + ((c ^ (row & 7)) << 4));
    }

    #pragma unroll
    for (int s = 0; s < STAGES - 1; s++) {
        const int kb = s * BK;
        #pragma unroll
        for (int t = 0; t < 8; t++)
            CP_ASYNC16(sb + s * STAGE_BYTES + soff[t], gptr[t] + kb);
        CP_ASYNC_COMMIT();
    }

    const int a_row = warp_m * 64 + (lane & 15);
    const int a_cs = lane >> 4;
    uint32_t aOff[4];
    #pragma unroll
    for (int fm = 0; fm < 4; fm++) {
        const int r = a_row + fm * 16;
        aOff[fm] = (uint32_t)(r * 128 + (((uint32_t)a_cs ^ (r & 7)) << 4));
    }
    const int b_row_in = (lane & 7) + ((lane >> 4) << 3);
    const int b_cs = (lane >> 3) & 1;
    uint32_t bOff[2];
    #pragma unroll
    for (int p = 0; p < 2; p++) {
        const int r = warp_n * 32 + p * 16 + b_row_in;
        bOff[p] = (uint32_t)(16384 + r * 128 + (((uint32_t)b_cs ^ (r & 7)) << 4));
    }

    float acc[4][4][4];
    #pragma unroll
    for (int i = 0; i < 4; i++)
        #pragma unroll
        for (int j = 0; j < 4; j++)
            #pragma unroll
            for (int k = 0; k < 4; k++) acc[i][j][k] = 0.f;

    uint32_t afr[2][4];
    uint32_t bfr[2][8];

    for (int kt = 0; kt < KT_ITERS; kt++) {
        CP_ASYNC_WAIT1();
        __syncthreads();

        const bool pf = (kt + STAGES - 1 < KT_ITERS);
        const int s = (kt + STAGES - 1) % STAGES;
        const int kb = (kt + STAGES - 1) * BK;
        const uint32_t stg = sb + (kt % STAGES) * STAGE_BYTES;

        LDSM_X4(bfr[0][0], bfr[0][1], bfr[0][2], bfr[0][3], stg + bOff[0]);
        LDSM_X4(bfr[0][4], bfr[0][5], bfr[0][6], bfr[0][7], stg + bOff[1]);
        LDSM_X4(afr[0][0], afr[0][1], afr[0][2], afr[0][3], stg + aOff[0]);

        #pragma unroll
        for (int k8 = 0; k8 < 4; k8++) {
            // spread next-stage cp.async: 2 chunks per k8
            if (pf) {
                CP_ASYNC16(sb + s * STAGE_BYTES + soff[2 * k8], gptr[2 * k8] + kb);
                CP_ASYNC16(sb + s * STAGE_BYTES + soff[2 * k8 + 1], gptr[2 * k8 + 1] + kb);
            }
            const int bcur = k8 & 1;
            const uint32_t kx = (uint32_t)(k8 << 5);
            if (k8 < 3) {
                const int bn = bcur ^ 1;
                const uint32_t kxn = (uint32_t)((k8 + 1) << 5);
                LDSM_X4(bfr[bn][0], bfr[bn][1], bfr[bn][2], bfr[bn][3],
                        stg + (bOff[0] ^ kxn));
                LDSM_X4(bfr[bn][4], bfr[bn][5], bfr[bn][6], bfr[bn][7],
                        stg + (bOff[1] ^ kxn));
            }
            #pragma unroll
            for (int fm = 0; fm < 4; fm++) {
                const int acur = (k8 * 4 + fm) & 1;
                if (fm < 3) {
                    const int an = acur ^ 1;
                    LDSM_X4(afr[an][0], afr[an][1], afr[an][2], afr[an][3],
                            stg + (aOff[fm + 1] ^ kx));
                } else if (k8 < 3) {
                    const int an = acur ^ 1;
                    const uint32_t kxn = (uint32_t)((k8 + 1) << 5);
                    LDSM_X4(afr[an][0], afr[an][1], afr[an][2], afr[an][3],
                            stg + (aOff[0] ^ kxn));
                }
                MMA_TF32(acc[fm][0], afr[acur][0], afr[acur][1], afr[acur][2],
                         afr[acur][3], bfr[bcur][0], bfr[bcur][1]);
                MMA_TF32(acc[fm][1], afr[acur][0], afr[acur][1], afr[acur][2],
                         afr[acur][3], bfr[bcur][2], bfr[bcur][3]);
                MMA_TF32(acc[fm][2], afr[acur][0], afr[acur][1], afr[acur][2],
                         afr[acur][3], bfr[bcur][4], bfr[bcur][5]);
                MMA_TF32(acc[fm][3], afr[acur][0], afr[acur][1], afr[acur][2],
                         afr[acur][3], bfr[bcur][6], bfr[bcur][7]);
            }
        }
        CP_ASYNC_COMMIT();
    }

    const int tr = lane >> 2;
    const int tc = (lane & 3) * 2;
    const int r_base = m0 + warp_m * 64;
    const int c_base = n0 + warp_n * 32;
    #pragma unroll
    for (int fn = 0; fn < 4; fn++) {
        const int col = c_base + fn * 8 + tc;
        const float2 bb = *(const float2*)&bias[col];
        #pragma unroll
        for (int fm = 0; fm < 4; fm++) {
            const int row0 = r_base + fm * 16 + tr;
            float2 v0, v1;
            v0.x = acc[fm][fn][0] + bb.x; v0.y = acc[fm][fn][1] + bb.y;
            v1.x = acc[fm][fn][2] + bb.x; v1.y = acc[fm][fn][3] + bb.y;
            *(float2*)&C[(size_t)row0 * Ntot + col] = v0;
            *(float2*)&C[(size_t)(row0 + 8) * Ntot + col] = v1;
        }
    }
}

// ---------------------------------------------------------------------------
// fused fp32 -> tf32 (RNA) prepass for all three inputs, one launch
// ---------------------------------------------------------------------------
#define N4_HID  ((S_LEN * D_HID) / 4)
#define N4_WQKV ((QKV_N * D_HID) / 4)
#define N4_WPRJ ((D_HID * D_HID) / 4)
#define N4_ALL  (N4_HID + N4_WQKV + N4_WPRJ)

__global__ void to_tf32_all(
    const float* __restrict__ hid, float* __restrict__ hid_t,
    const float* __restrict__ wqkv, float* __restrict__ wqkv_t,
    const float* __restrict__ wprj, float* __restrict__ wprj_t)
{
    int i = blockIdx.x * blockDim.x + threadIdx.x;
    const float4* src;
    float4* dst;
    if (i < N4_HID) {
        src = (const float4*)hid; dst = (float4*)hid_t;
    } else if (i < N4_HID + N4_WQKV) {
        i -= N4_HID;
        src = (const float4*)wqkv; dst = (float4*)wqkv_t;
    } else if (i < N4_ALL) {
        i -= N4_HID + N4_WQKV;
        src = (const float4*)wprj; dst = (float4*)wprj_t;
    } else {
        return;
    }
    float4 v = src[i];
    v.x = to_tf32f(v.x); v.y = to_tf32f(v.y);
    v.z = to_tf32f(v.z); v.w = to_tf32f(v.w);
    dst[i] = v;
}

// ---------------------------------------------------------------------------
// Windowed attention v3.2 -- tensor-core QK^T and PV; output staged through
// smem (vT region, consumed by then) for coalesced float4 stores.
// ---------------------------------------------------------------------------
#define QS_LD 84    // Q/K rows: 336B (21 16B-units, odd)
#define PS_LD 68    // P rows:   272B (17 units, odd); aliases Q region
#define VT_LD 68    // V^T rows: 272B
#define OS_LD 80    // O stage rows: 320B (reuses vT region; 64*80 <= 80*68)
#define ATTN_SMEM ((64 * QS_LD + 64 * QS_LD + 80 * VT_LD) * (int)sizeof(float))  // 64768

__global__ void __launch_bounds__(128, 3) attn_kernel(
    const float* __restrict__ qkv,
    const float* __restrict__ mask,
    const float* __restrict__ cosv,
    const float* __restrict__ sinv,
    float* __restrict__ out_t)
{
    extern __shared__ float sm[];
    float* qs = sm;                      // 64 x 84 (Q; later aliased by P @68)
    float* ks = qs + 64 * QS_LD;         // 64 x 84
    float* vT = ks + 64 * QS_LD;         // 80 x 68 (transposed V, tf32-rounded)
    float* ps = qs;                      // P alias, stride 68
    float* os = vT;                      // O stage alias, stride 80

    const uint32_t sb = smem_u32(sm);
    const uint32_t qs_b = sb;
    const uint32_t ks_b = sb + 64 * QS_LD * 4;
    const uint32_t vT_b = ks_b + 64 * QS_LD * 4;

    const int w = blockIdx.x >> 4;
    const int h = blockIdx.x & 15;
    const int tid = threadIdx.x;
    const int fm = tid >> 5, lane = tid & 31;

    // ---- phase 1: merged q/k fused RoPE (cos/sin once), V transposed ----
    for (int u = tid; u < 1920; u += 128) {
        if (u < 640) {
            const int p = u / 10, d4 = (u % 10) * 4;
            const int s = w * WS_WIN + p;
            const float4 c0 = *(const float4*)(cosv + s * HD_DIM + d4);
            const float4 c1 = *(const float4*)(cosv + s * HD_DIM + d4 + 40);
            const float4 s0 = *(const float4*)(sinv + s * HD_DIM + d4);
            const float4 s1 = *(const float4*)(sinv + s * HD_DIM + d4 + 40);
            const float* srcq = qkv + (size_t)s * QKV_N + h * HD_DIM;
            const float* srck = srcq + D_HID;

            const float4 qa = *(const float4*)(srcq + d4);
            const float4 qb = *(const float4*)(srcq + d4 + 40);
            float4 qlo, qhi;
            qlo.x = qa.x * c0.x - qb.x * s0.x;  qhi.x = qb.x * c1.x + qa.x * s1.x;
            qlo.y = qa.y * c0.y - qb.y * s0.y;  qhi.y = qb.y * c1.y + qa.y * s1.y;
            qlo.z = qa.z * c0.z - qb.z * s0.z;  qhi.z = qb.z * c1.z + qa.z * s1.z;
            qlo.w = qa.w * c0.w - qb.w * s0.w;  qhi.w = qb.w * c1.w + qa.w * s1.w;
            float* qdst = qs + p * QS_LD + d4;
            *(float4*)qdst = qlo;
            *(float4*)(qdst + 40) = qhi;

            const float4 ka = *(const float4*)(srck + d4);
            const float4 kb = *(const float4*)(srck + d4 + 40);
            float4 klo, khi;
            klo.x = ka.x * c0.x - kb.x * s0.x;  khi.x = kb.x * c1.x + ka.x * s1.x;
            klo.y = ka.y * c0.y - kb.y * s0.y;  khi.y = kb.y * c1.y + ka.y * s1.y;
            klo.z = ka.z * c0.z - kb.z * s0.z;  khi.z = kb.z * c1.z + ka.z * s1.z;
            klo.w = ka.w * c0.w - kb.w * s0.w;  khi.w = kb.w * c1.w + ka.w * s1.w;
            float* kdst = ks + p * QS_LD + d4;
            *(float4*)kdst = klo;
            *(float4*)(kdst + 40) = khi;
        } else {
            const int li = u - 640;
            const int p = li / 20, c4 = (li % 20) * 4;
            const int s = w * WS_WIN + p;
            const float4 v = *(const float4*)&qkv[(size_t)s * QKV_N + 2 * D_HID + h * HD_DIM + c4];
            vT[(c4 + 0) * VT_LD + p] = to_tf32f(v.x);
            vT[(c4 + 1) * VT_LD + p] = to_tf32f(v.y);
            vT[(c4 + 2) * VT_LD + p] = to_tf32f(v.z);
            vT[(c4 + 3) * VT_LD + p] = to_tf32f(v.w);
        }
    }
    __syncthreads();

    // ---- QK^T via tf32 mma, x2-split (Ah Bh + Ah Bl + Al Bh) ----
    const uint32_t aQ = qs_b + (uint32_t)((fm * 16 + (lane & 15)) * (QS_LD * 4)
                                          + (lane >> 4) * 16);
    uint32_t bK[4];
    #pragma unroll
    for (int p = 0; p < 4; p++)
        bK[p] = ks_b + (uint32_t)((p * 16 + (lane & 7) + ((lane >> 4) << 3)) * (QS_LD * 4)
                                  + ((lane >> 3) & 1) * 16);

    float S[8][4];
    #pragma unroll
    for (int i = 0; i < 8; i++)
        #pragma unroll
        for (int j = 0; j < 4; j++) S[i][j] = 0.f;

    #pragma unroll
    for (int k8 = 0; k8 < 10; k8++) {
        uint32_t a0, a1, a2, a3;
        LDSM_X4(a0, a1, a2, a3, aQ + k8 * 32);
        uint32_t ah[4], al[4];
        split_tf32(a0, ah[0], al[0]); split_tf32(a1, ah[1], al[1]);
        split_tf32(a2, ah[2], al[2]); split_tf32(a3, ah[3], al[3]);
        #pragma unroll
        for (int p = 0; p < 4; p++) {
            uint32_t b0, b1, b2, b3;
            LDSM_X4(b0, b1, b2, b3, bK[p] + k8 * 32);
            uint32_t bh[4], bl[4];
            split_tf32(b0, bh[0], bl[0]); split_tf32(b1, bh[1], bl[1]);
            split_tf32(b2, bh[2], bl[2]); split_tf32(b3, bh[3], bl[3]);
            MMA_TF32(S[2 * p],     ah[0], ah[1], ah[2], ah[3], bh[0], bh[1]);
            MMA_TF32(S[2 * p + 1], ah[0], ah[1], ah[2], ah[3], bh[2], bh[3]);
            MMA_TF32(S[2 * p],     ah[0], ah[1], ah[2], ah[3], bl[0], bl[1]);
            MMA_TF32(S[2 * p + 1], ah[0], ah[1], ah[2], ah[3], bl[2], bl[3]);
            MMA_TF32(S[2 * p],     al[0], al[1], al[2], al[3], bh[0], bh[1]);
            MMA_TF32(S[2 * p + 1], al[0], al[1], al[2], al[3], bh[2], bh[3]);
        }
    }

    // ---- softmax on fragments ----
    const int tr = lane >> 2;
    const int rA = fm * 16 + tr, rB = rA + 8;
    const int cb = (lane & 3) * 2;
    const float scale = 0.1118033988749895f;
    const float* mrow = mask + (size_t)w * (WS_WIN * WS_WIN);

    float mxA = -1e30f, mxB = -1e30f;
    #pragma unroll
    for (int fn = 0; fn < 8; fn++) {
        const int c = fn * 8 + cb;
        const float2 mA = *(const float2*)&mrow[rA * WS_WIN + c];
        const float2 mB = *(const float2*)&mrow[rB * WS_WIN + c];
        S[fn][0] = S[fn][0] * scale + mA.x;
        S[fn][1] = S[fn][1] * scale + mA.y;
        S[fn][2] = S[fn][2] * scale + mB.x;
        S[fn][3] = S[fn][3] * scale + mB.y;
        mxA = fmaxf(mxA, fmaxf(S[fn][0], S[fn][1]));
        mxB = fmaxf(mxB, fmaxf(S[fn][2], S[fn][3]));
    }
    mxA = fmaxf(mxA, __shfl_xor_sync(0xffffffffu, mxA, 1));
    mxA = fmaxf(mxA, __shfl_xor_sync(0xffffffffu, mxA, 2));
    mxB = fmaxf(mxB, __shfl_xor_sync(0xffffffffu, mxB, 1));
    mxB = fmaxf(mxB, __shfl_xor_sync(0xffffffffu, mxB, 2));

    float sA = 0.f, sB = 0.f;
    #pragma unroll
    for (int fn = 0; fn < 8; fn++) {
        S[fn][0] = __expf(S[fn][0] - mxA);
        S[fn][1] = __expf(S[fn][1] - mxA);
        S[fn][2] = __expf(S[fn][2] - mxB);
        S[fn][3] = __expf(S[fn][3] - mxB);
        sA += S[fn][0] + S[fn][1];
        sB += S[fn][2] + S[fn][3];
    }
    sA += __shfl_xor_sync(0xffffffffu, sA, 1);
    sA += __shfl_xor_sync(0xffffffffu, sA, 2);
    sB += __shfl_xor_sync(0xffffffffu, sB, 1);
    sB += __shfl_xor_sync(0xffffffffu, sB, 2);
    const float invA = 1.f / sA, invB = 1.f / sB;

    // all warps must finish reading Q before P overwrites the qs region
    __syncthreads();

    #pragma unroll
    for (int fn = 0; fn < 8; fn++) {
        const int c = fn * 8 + cb;
        float2 pA, pB;
        pA.x = to_tf32f(S[fn][0] * invA); pA.y = to_tf32f(S[fn][1] * invA);
        pB.x = to_tf32f(S[fn][2] * invB); pB.y = to_tf32f(S[fn][3] * invB);
        *(float2*)&ps[rA * PS_LD + c] = pA;
        *(float2*)&ps[rB * PS_LD + c] = pB;
    }
    __syncwarp();   // each warp reads only its own P rows below

    // ---- PV via tf32 mma: O[rows16fm x 80] = P[16 x 64] * vT^T ----
    const uint32_t aP = qs_b + (uint32_t)((fm * 16 + (lane & 15)) * (PS_LD * 4)
                                          + (lane >> 4) * 16);
    uint32_t bV[5];
    #pragma unroll
    for (int p = 0; p < 5; p++)
        bV[p] = vT_b + (uint32_t)((p * 16 + (lane & 7) + ((lane >> 4) << 3)) * (VT_LD * 4)
                                  + ((lane >> 3) & 1) * 16);

    float O[10][4];
    #pragma unroll
    for (int i = 0; i < 10; i++)
        #pragma unroll
        for (int j = 0; j < 4; j++) O[i][j] = 0.f;

    #pragma unroll
    for (int k8 = 0; k8 < 8; k8++) {
        uint32_t a0, a1, a2, a3;
        LDSM_X4(a0, a1, a2, a3, aP + k8 * 32);
        #pragma unroll
        for (int p = 0; p < 5; p++) {
            uint32_t b0, b1, b2, b3;
            LDSM_X4(b0, b1, b2, b3, bV[p] + k8 * 32);
            MMA_TF32(O[2 * p],     a0, a1, a2, a3, b0, b1);
            MMA_TF32(O[2 * p + 1], a0, a1, a2, a3, b2, b3);
        }
    }

    // ---- stage O in smem (vT region, now consumed), then coalesced stores ----
    __syncthreads();   // all warps done reading vT
    #pragma unroll
    for (int fn = 0; fn < 10; fn++) {
        const int c = fn * 8 + cb;
        float2 a2, b2;
        a2.x = to_tf32f(O[fn][0]); a2.y = to_tf32f(O[fn][1]);
        b2.x = to_tf32f(O[fn][2]); b2.y = to_tf32f(O[fn][3]);
        *(float2*)&os[rA * OS_LD + c] = a2;
        *(float2*)&os[rB * OS_LD + c] = b2;
    }
    __syncthreads();

    for (int u = tid; u < 64 * 20; u += 128) {
        const int r = u / 20, c4 = (u % 20) * 4;
        const float4 v = *(const float4*)&os[r * OS_LD + c4];
        *(float4*)&out_t[(size_t)(w * WS_WIN + r) * D_HID + h * HD_DIM + c4] = v;
    }
}

// ---------------------------------------------------------------------------
// launch
// ---------------------------------------------------------------------------
extern "C" void kernel_launch(void* const* d_in, const int* in_sizes, int n_in,
                              void* d_out, int out_size)
{
    (void)in_sizes; (void)n_in; (void)out_size;
    const float* hidden = (const float*)d_in[0];
    const float* masks  = (const float*)d_in[1];
    const float* cosv   = (const float*)d_in[2];
    const float* sinv   = (const float*)d_in[3];
    const float* qkv_w  = (const float*)d_in[4];
    const float* qkv_b  = (const float*)d_in[5];
    const float* proj_w = (const float*)d_in[6];
    const float* proj_b = (const float*)d_in[7];
    float* out = (float*)d_out;

    float *qkv_buf, *hid_t, *wqkv_t, *wproj_t, *attn_t;
    cudaGetSymbolAddress((void**)&qkv_buf, g_qkv);
    cudaGetSymbolAddress((void**)&hid_t, g_hid_t);
    cudaGetSymbolAddress((void**)&wqkv_t, g_wqkv_t);
    cudaGetSymbolAddress((void**)&wproj_t, g_wproj_t);
    cudaGetSymbolAddress((void**)&attn_t, g_attn_t);

    // 0) fused fp32 -> tf32 rounding prepass (one launch)
    to_tf32_all<<<(N4_ALL + 255) / 256, 256>>>(hidden, hid_t, qkv_w, wqkv_t,
                                               proj_w, wproj_t);

    // 1) QKV projection (mma.sync tf32): [S,1280] x [3840,1280]^T + b
    {
        cudaFuncSetAttribute(gemm_tf32, cudaFuncAttributeMaxDynamicSharedMemorySize, GEMM_SMEM);
        dim3 grid(QKV_N / BN, S_LEN / BM);
        gemm_tf32<<<grid, 256, GEMM_SMEM>>>(hid_t, wqkv_t, qkv_b, qkv_buf, QKV_N);
    }

    // 2) windowed attention v3.2 (tensor-core QK^T/PV, coalesced output)
    {
        cudaFuncSetAttribute(attn_kernel, cudaFuncAttributeMaxDynamicSharedMemorySize, ATTN_SMEM);
        attn_kernel<<<NW_WIN * H_NUM, 128, ATTN_SMEM>>>(qkv_buf, masks, cosv, sinv, attn_t);
    }

    // 3) output projection (mma.sync tf32): [S,1280] x [1280,1280]^T + b
    {
        dim3 grid(D_HID / BN, S_LEN / BM);
        gemm_tf32<<<grid, 256, GEMM_SMEM>>>(attn_t, wproj_t, proj_b, out, D_HID);
    }
}

// round 17
// speedup vs baseline: 1.0082x; 1.0082x over previous
#include <cuda_runtime.h>
#include <cuda_bf16.h>
#include <cstdint>
#include <cstddef>

// ---------------------------------------------------------------------------
// Problem constants
// ---------------------------------------------------------------------------
#define S_LEN 16384
#define D_HID 1280
#define H_NUM 16
#define HD_DIM 80
#define WS_WIN 64
#define NW_WIN (S_LEN / WS_WIN)   // 256
#define QKV_N (3 * D_HID)         // 3840
#define KDIM 1280

// GEMM tiling: CTA 128x128, BK=32 fp32, 8 warps (2Mx4N), warp tile 64x32.
#define BM 128
#define BN 128
#define BK 32
#define STAGES 3
#define KT_ITERS (KDIM / BK)      // 40
#define STAGE_BYTES 32768         // A 16K | B 16K
#define GEMM_SMEM (STAGES * STAGE_BYTES)   // 98304

// ---------------------------------------------------------------------------
// Scratch (device globals: allocation-free contract)
// ---------------------------------------------------------------------------
__device__ float g_qkv[(size_t)S_LEN * QKV_N];     // fp32 qkv output
__device__ float g_hid_t[(size_t)S_LEN * D_HID];   // tf32-rounded hidden
__device__ float g_wqkv_t[(size_t)QKV_N * D_HID];  // tf32-rounded qkv weight
__device__ float g_wproj_t[(size_t)D_HID * D_HID]; // tf32-rounded proj weight
__device__ float g_attn_t[(size_t)S_LEN * D_HID];  // tf32-rounded attn output

// ---------------------------------------------------------------------------
// PTX helpers (baseline sm_80+ only -- harness targets plain sm_100)
// ---------------------------------------------------------------------------
__device__ __forceinline__ uint32_t smem_u32(const void* p) {
    uint32_t a;
    asm("{ .reg .u64 t; cvta.to.shared.u64 t, %1; cvt.u32.u64 %0, t; }"
        : "=r"(a) : "l"(p));
    return a;
}

__device__ __forceinline__ float to_tf32f(float x) {
    uint32_t v;
    asm("cvt.rna.tf32.f32 %0, %1;" : "=r"(v) : "f"(x));
    return __uint_as_float(v);
}

// split fp32 bits into tf32 hi + tf32 lo (x = hi + lo + O(2^-24))
__device__ __forceinline__ void split_tf32(uint32_t x, uint32_t& h, uint32_t& l) {
    const float xf = __uint_as_float(x);
    uint32_t hb;
    asm("cvt.rna.tf32.f32 %0, %1;" : "=r"(hb) : "f"(xf));
    const float r = xf - __uint_as_float(hb);
    asm("cvt.rna.tf32.f32 %0, %1;" : "=r"(l) : "f"(r));
    h = hb;
}

#define CP_ASYNC16(smem_addr, gptr) \
    asm volatile("cp.async.cg.shared.global [%0], [%1], 16;\n" \
                 :: "r"(smem_addr), "l"(gptr))
#define CP_ASYNC_COMMIT() asm volatile("cp.async.commit_group;\n" ::: "memory")
#define CP_ASYNC_WAIT1()  asm volatile("cp.async.wait_group 1;\n" ::: "memory")

#define LDSM_X4(r0, r1, r2, r3, addr) \
    asm volatile("ldmatrix.sync.aligned.m8n8.x4.shared.b16 {%0,%1,%2,%3}, [%4];" \
                 : "=r"(r0), "=r"(r1), "=r"(r2), "=r"(r3) : "r"(addr))

#define MMA_TF32(d, a0, a1, a2, a3, b0, b1) \
    asm volatile("mma.sync.aligned.m16n8k8.row.col.f32.tf32.tf32.f32 " \
                 "{%0,%1,%2,%3}, {%4,%5,%6,%7}, {%8,%9}, {%0,%1,%2,%3};" \
                 : "+f"((d)[0]), "+f"((d)[1]), "+f"((d)[2]), "+f"((d)[3]) \
                 : "r"(a0), "r"(a1), "r"(a2), "r"(a3), "r"(b0), "r"(b1))

// ---------------------------------------------------------------------------
// tf32 mma.sync GEMM (R15-exact: verified fastest configuration)
// ---------------------------------------------------------------------------
__global__ void __launch_bounds__(256, 2) gemm_tf32(
    const float* __restrict__ A, const float* __restrict__ B,
    const float* __restrict__ bias, float* __restrict__ C, int Ntot)
{
    extern __shared__ char smem[];
    const uint32_t sb = smem_u32(smem);
    const int tid = threadIdx.x;
    const int wid = tid >> 5, lane = tid & 31;
    const int warp_m = wid & 1;
    const int warp_n = wid >> 1;
    const int m0 = blockIdx.y * BM;
    const int n0 = blockIdx.x * BN;

    const float* gptr[8];
    uint32_t soff[8];
    #pragma unroll
    for (int t = 0; t < 8; t++) {
        const int idx = tid + t * 256;
        int row, c;
        uint32_t mbase;
        const float* base;
        int r0;
        if (idx < 1024) {
            row = idx >> 3; c = idx & 7;
            base = A; mbase = 0; r0 = m0 + row;
        } else {
            const int j = idx - 1024;
            row = j >> 3; c = j & 7;
            base = B; mbase = 16384; r0 = n0 + row;
        }
        gptr[t] = base + (size_t)r0 * KDIM + c * 4;
        soff[t] = mbase + (uint32_t)(row * 128 + ((c ^ (row & 7)) << 4));
    }

    #pragma unroll
    for (int s = 0; s < STAGES - 1; s++) {
        const int kb = s * BK;
        #pragma unroll
        for (int t = 0; t < 8; t++)
            CP_ASYNC16(sb + s * STAGE_BYTES + soff[t], gptr[t] + kb);
        CP_ASYNC_COMMIT();
    }

    const int a_row = warp_m * 64 + (lane & 15);
    const int a_cs = lane >> 4;
    uint32_t aOff[4];
    #pragma unroll
    for (int fm = 0; fm < 4; fm++) {
        const int r = a_row + fm * 16;
        aOff[fm] = (uint32_t)(r * 128 + (((uint32_t)a_cs ^ (r & 7)) << 4));
    }
    const int b_row_in = (lane & 7) + ((lane >> 4) << 3);
    const int b_cs = (lane >> 3) & 1;
    uint32_t bOff[2];
    #pragma unroll
    for (int p = 0; p < 2; p++) {
        const int r = warp_n * 32 + p * 16 + b_row_in;
        bOff[p] = (uint32_t)(16384 + r * 128 + (((uint32_t)b_cs ^ (r & 7)) << 4));
    }

    float acc[4][4][4];
    #pragma unroll
    for (int i = 0; i < 4; i++)
        #pragma unroll
        for (int j = 0; j < 4; j++)
            #pragma unroll
            for (int k = 0; k < 4; k++) acc[i][j][k] = 0.f;

    uint32_t afr[2][4];
    uint32_t bfr[2][8];

    for (int kt = 0; kt < KT_ITERS; kt++) {
        CP_ASYNC_WAIT1();
        __syncthreads();

        if (kt + STAGES - 1 < KT_ITERS) {
            const int s = (kt + STAGES - 1) % STAGES;
            const int kb = (kt + STAGES - 1) * BK;
            #pragma unroll
            for (int t = 0; t < 8; t++)
                CP_ASYNC16(sb + s * STAGE_BYTES + soff[t], gptr[t] + kb);
        }
        CP_ASYNC_COMMIT();

        const uint32_t stg = sb + (kt % STAGES) * STAGE_BYTES;

        LDSM_X4(bfr[0][0], bfr[0][1], bfr[0][2], bfr[0][3], stg + bOff[0]);
        LDSM_X4(bfr[0][4], bfr[0][5], bfr[0][6], bfr[0][7], stg + bOff[1]);
        LDSM_X4(afr[0][0], afr[0][1], afr[0][2], afr[0][3], stg + aOff[0]);

        #pragma unroll
        for (int k8 = 0; k8 < 4; k8++) {
            const int bcur = k8 & 1;
            const uint32_t kx = (uint32_t)(k8 << 5);
            if (k8 < 3) {
                const int bn = bcur ^ 1;
                const uint32_t kxn = (uint32_t)((k8 + 1) << 5);
                LDSM_X4(bfr[bn][0], bfr[bn][1], bfr[bn][2], bfr[bn][3],
                        stg + (bOff[0] ^ kxn));
                LDSM_X4(bfr[bn][4], bfr[bn][5], bfr[bn][6], bfr[bn][7],
                        stg + (bOff[1] ^ kxn));
            }
            #pragma unroll
            for (int fm = 0; fm < 4; fm++) {
                const int acur = (k8 * 4 + fm) & 1;
                if (fm < 3) {
                    const int an = acur ^ 1;
                    LDSM_X4(afr[an][0], afr[an][1], afr[an][2], afr[an][3],
                            stg + (aOff[fm + 1] ^ kx));
                } else if (k8 < 3) {
                    const int an = acur ^ 1;
                    const uint32_t kxn = (uint32_t)((k8 + 1) << 5);
                    LDSM_X4(afr[an][0], afr[an][1], afr[an][2], afr[an][3],
                            stg + (aOff[0] ^ kxn));
                }
                MMA_TF32(acc[fm][0], afr[acur][0], afr[acur][1], afr[acur][2],
                         afr[acur][3], bfr[bcur][0], bfr[bcur][1]);
                MMA_TF32(acc[fm][1], afr[acur][0], afr[acur][1], afr[acur][2],
                         afr[acur][3], bfr[bcur][2], bfr[bcur][3]);
                MMA_TF32(acc[fm][2], afr[acur][0], afr[acur][1], afr[acur][2],
                         afr[acur][3], bfr[bcur][4], bfr[bcur][5]);
                MMA_TF32(acc[fm][3], afr[acur][0], afr[acur][1], afr[acur][2],
                         afr[acur][3], bfr[bcur][6], bfr[bcur][7]);
            }
        }
    }

    const int tr = lane >> 2;
    const int tc = (lane & 3) * 2;
    const int r_base = m0 + warp_m * 64;
    const int c_base = n0 + warp_n * 32;
    #pragma unroll
    for (int fn = 0; fn < 4; fn++) {
        const int col = c_base + fn * 8 + tc;
        const float2 bb = *(const float2*)&bias[col];
        #pragma unroll
        for (int fm = 0; fm < 4; fm++) {
            const int row0 = r_base + fm * 16 + tr;
            float2 v0, v1;
            v0.x = acc[fm][fn][0] + bb.x; v0.y = acc[fm][fn][1] + bb.y;
            v1.x = acc[fm][fn][2] + bb.x; v1.y = acc[fm][fn][3] + bb.y;
            *(float2*)&C[(size_t)row0 * Ntot + col] = v0;
            *(float2*)&C[(size_t)(row0 + 8) * Ntot + col] = v1;
        }
    }
}

// ---------------------------------------------------------------------------
// fused fp32 -> tf32 (RNA) prepass: hidden + qkv weight only (wproj is
// converted inside the attention launch, overlapping with attention work)
// ---------------------------------------------------------------------------
#define N4_HID  ((S_LEN * D_HID) / 4)
#define N4_WQKV ((QKV_N * D_HID) / 4)
#define N4_WPRJ ((D_HID * D_HID) / 4)
#define N4_PRE  (N4_HID + N4_WQKV)

__global__ void to_tf32_pre(
    const float* __restrict__ hid, float* __restrict__ hid_t,
    const float* __restrict__ wqkv, float* __restrict__ wqkv_t)
{
    int i = blockIdx.x * blockDim.x + threadIdx.x;
    const float4* src;
    float4* dst;
    if (i < N4_HID) {
        src = (const float4*)hid; dst = (float4*)hid_t;
    } else if (i < N4_PRE) {
        i -= N4_HID;
        src = (const float4*)wqkv; dst = (float4*)wqkv_t;
    } else {
        return;
    }
    float4 v = src[i];
    v.x = to_tf32f(v.x); v.y = to_tf32f(v.y);
    v.z = to_tf32f(v.z); v.w = to_tf32f(v.w);
    dst[i] = v;
}

// ---------------------------------------------------------------------------
// Windowed attention v3.1 (R15-exact math) + piggybacked wproj conversion:
// blocks >= 4096 convert wproj fp32->tf32 (grid-stride) and exit.
// ---------------------------------------------------------------------------
#define QS_LD 84    // Q/K rows: 336B (21 16B-units, odd)
#define PS_LD 68    // P rows:   272B (17 units, odd); aliases Q region
#define VT_LD 68    // V^T rows: 272B
#define ATTN_SMEM ((64 * QS_LD + 64 * QS_LD + 80 * VT_LD) * (int)sizeof(float))  // 64768
#define ATTN_BLOCKS (NW_WIN * H_NUM)     // 4096
#define CONV_BLOCKS 416                  // 416*128 = 53248 threads for wproj

__global__ void __launch_bounds__(128, 3) attn_kernel(
    const float* __restrict__ qkv,
    const float* __restrict__ mask,
    const float* __restrict__ cosv,
    const float* __restrict__ sinv,
    float* __restrict__ out_t,
    const float* __restrict__ wprj,
    float* __restrict__ wprj_t)
{
    // ---- piggyback blocks: wproj fp32 -> tf32 conversion ----
    if (blockIdx.x >= ATTN_BLOCKS) {
        const int tid0 = (blockIdx.x - ATTN_BLOCKS) * 128 + threadIdx.x;
        for (int i = tid0; i < N4_WPRJ; i += CONV_BLOCKS * 128) {
            float4 v = ((const float4*)wprj)[i];
            v.x = to_tf32f(v.x); v.y = to_tf32f(v.y);
            v.z = to_tf32f(v.z); v.w = to_tf32f(v.w);
            ((float4*)wprj_t)[i] = v;
        }
        return;
    }

    extern __shared__ float sm[];
    float* qs = sm;                      // 64 x 84 (Q; later aliased by P @68)
    float* ks = qs + 64 * QS_LD;         // 64 x 84
    float* vT = ks + 64 * QS_LD;         // 80 x 68 (transposed V, tf32-rounded)
    float* ps = qs;                      // P alias, stride 68

    const uint32_t sb = smem_u32(sm);
    const uint32_t qs_b = sb;
    const uint32_t ks_b = sb + 64 * QS_LD * 4;
    const uint32_t vT_b = ks_b + 64 * QS_LD * 4;

    const int w = blockIdx.x >> 4;
    const int h = blockIdx.x & 15;
    const int tid = threadIdx.x;
    const int fm = tid >> 5, lane = tid & 31;

    // ---- phase 1: merged q/k fused RoPE (cos/sin once), V transposed ----
    for (int u = tid; u < 1920; u += 128) {
        if (u < 640) {
            const int p = u / 10, d4 = (u % 10) * 4;
            const int s = w * WS_WIN + p;
            const float4 c0 = *(const float4*)(cosv + s * HD_DIM + d4);
            const float4 c1 = *(const float4*)(cosv + s * HD_DIM + d4 + 40);
            const float4 s0 = *(const float4*)(sinv + s * HD_DIM + d4);
            const float4 s1 = *(const float4*)(sinv + s * HD_DIM + d4 + 40);
            const float* srcq = qkv + (size_t)s * QKV_N + h * HD_DIM;
            const float* srck = srcq + D_HID;

            const float4 qa = *(const float4*)(srcq + d4);
            const float4 qb = *(const float4*)(srcq + d4 + 40);
            float4 qlo, qhi;
            qlo.x = qa.x * c0.x - qb.x * s0.x;  qhi.x = qb.x * c1.x + qa.x * s1.x;
            qlo.y = qa.y * c0.y - qb.y * s0.y;  qhi.y = qb.y * c1.y + qa.y * s1.y;
            qlo.z = qa.z * c0.z - qb.z * s0.z;  qhi.z = qb.z * c1.z + qa.z * s1.z;
            qlo.w = qa.w * c0.w - qb.w * s0.w;  qhi.w = qb.w * c1.w + qa.w * s1.w;
            float* qdst = qs + p * QS_LD + d4;
            *(float4*)qdst = qlo;
            *(float4*)(qdst + 40) = qhi;

            const float4 ka = *(const float4*)(srck + d4);
            const float4 kb = *(const float4*)(srck + d4 + 40);
            float4 klo, khi;
            klo.x = ka.x * c0.x - kb.x * s0.x;  khi.x = kb.x * c1.x + ka.x * s1.x;
            klo.y = ka.y * c0.y - kb.y * s0.y;  khi.y = kb.y * c1.y + ka.y * s1.y;
            klo.z = ka.z * c0.z - kb.z * s0.z;  khi.z = kb.z * c1.z + ka.z * s1.z;
            klo.w = ka.w * c0.w - kb.w * s0.w;  khi.w = kb.w * c1.w + ka.w * s1.w;
            float* kdst = ks + p * QS_LD + d4;
            *(float4*)kdst = klo;
            *(float4*)(kdst + 40) = khi;
        } else {
            const int li = u - 640;
            const int p = li / 20, c4 = (li % 20) * 4;
            const int s = w * WS_WIN + p;
            const float4 v = *(const float4*)&qkv[(size_t)s * QKV_N + 2 * D_HID + h * HD_DIM + c4];
            vT[(c4 + 0) * VT_LD + p] = to_tf32f(v.x);
            vT[(c4 + 1) * VT_LD + p] = to_tf32f(v.y);
            vT[(c4 + 2) * VT_LD + p] = to_tf32f(v.z);
            vT[(c4 + 3) * VT_LD + p] = to_tf32f(v.w);
        }
    }
    __syncthreads();

    // ---- QK^T via tf32 mma, x2-split (Ah Bh + Ah Bl + Al Bh) ----
    const uint32_t aQ = qs_b + (uint32_t)((fm * 16 + (lane & 15)) * (QS_LD * 4)
                                          + (lane >> 4) * 16);
    uint32_t bK[4];
    #pragma unroll
    for (int p = 0; p < 4; p++)
        bK[p] = ks_b + (uint32_t)((p * 16 + (lane & 7) + ((lane >> 4) << 3)) * (QS_LD * 4)
                                  + ((lane >> 3) & 1) * 16);

    float S[8][4];
    #pragma unroll
    for (int i = 0; i < 8; i++)
        #pragma unroll
        for (int j = 0; j < 4; j++) S[i][j] = 0.f;

    #pragma unroll
    for (int k8 = 0; k8 < 10; k8++) {
        uint32_t a0, a1, a2, a3;
        LDSM_X4(a0, a1, a2, a3, aQ + k8 * 32);
        uint32_t ah[4], al[4];
        split_tf32(a0, ah[0], al[0]); split_tf32(a1, ah[1], al[1]);
        split_tf32(a2, ah[2], al[2]); split_tf32(a3, ah[3], al[3]);
        #pragma unroll
        for (int p = 0; p < 4; p++) {
            uint32_t b0, b1, b2, b3;
            LDSM_X4(b0, b1, b2, b3, bK[p] + k8 * 32);
            uint32_t bh[4], bl[4];
            split_tf32(b0, bh[0], bl[0]); split_tf32(b1, bh[1], bl[1]);
            split_tf32(b2, bh[2], bl[2]); split_tf32(b3, bh[3], bl[3]);
            MMA_TF32(S[2 * p],     ah[0], ah[1], ah[2], ah[3], bh[0], bh[1]);
            MMA_TF32(S[2 * p + 1], ah[0], ah[1], ah[2], ah[3], bh[2], bh[3]);
            MMA_TF32(S[2 * p],     ah[0], ah[1], ah[2], ah[3], bl[0], bl[1]);
            MMA_TF32(S[2 * p + 1], ah[0], ah[1], ah[2], ah[3], bl[2], bl[3]);
            MMA_TF32(S[2 * p],     al[0], al[1], al[2], al[3], bh[0], bh[1]);
            MMA_TF32(S[2 * p + 1], al[0], al[1], al[2], al[3], bh[2], bh[3]);
        }
    }

    // ---- softmax on fragments ----
    const int tr = lane >> 2;
    const int rA = fm * 16 + tr, rB = rA + 8;
    const int cb = (lane & 3) * 2;
    const float scale = 0.1118033988749895f;
    const float* mrow = mask + (size_t)w * (WS_WIN * WS_WIN);

    float mxA = -1e30f, mxB = -1e30f;
    #pragma unroll
    for (int fn = 0; fn < 8; fn++) {
        const int c = fn * 8 + cb;
        const float2 mA = *(const float2*)&mrow[rA * WS_WIN + c];
        const float2 mB = *(const float2*)&mrow[rB * WS_WIN + c];
        S[fn][0] = S[fn][0] * scale + mA.x;
        S[fn][1] = S[fn][1] * scale + mA.y;
        S[fn][2] = S[fn][2] * scale + mB.x;
        S[fn][3] = S[fn][3] * scale + mB.y;
        mxA = fmaxf(mxA, fmaxf(S[fn][0], S[fn][1]));
        mxB = fmaxf(mxB, fmaxf(S[fn][2], S[fn][3]));
    }
    mxA = fmaxf(mxA, __shfl_xor_sync(0xffffffffu, mxA, 1));
    mxA = fmaxf(mxA, __shfl_xor_sync(0xffffffffu, mxA, 2));
    mxB = fmaxf(mxB, __shfl_xor_sync(0xffffffffu, mxB, 1));
    mxB = fmaxf(mxB, __shfl_xor_sync(0xffffffffu, mxB, 2));

    float sA = 0.f, sB = 0.f;
    #pragma unroll
    for (int fn = 0; fn < 8; fn++) {
        S[fn][0] = __expf(S[fn][0] - mxA);
        S[fn][1] = __expf(S[fn][1] - mxA);
        S[fn][2] = __expf(S[fn][2] - mxB);
        S[fn][3] = __expf(S[fn][3] - mxB);
        sA += S[fn][0] + S[fn][1];
        sB += S[fn][2] + S[fn][3];
    }
    sA += __shfl_xor_sync(0xffffffffu, sA, 1);
    sA += __shfl_xor_sync(0xffffffffu, sA, 2);
    sB += __shfl_xor_sync(0xffffffffu, sB, 1);
    sB += __shfl_xor_sync(0xffffffffu, sB, 2);
    const float invA = 1.f / sA, invB = 1.f / sB;

    // all warps must finish reading Q before P overwrites the qs region
    __syncthreads();

    #pragma unroll
    for (int fn = 0; fn < 8; fn++) {
        const int c = fn * 8 + cb;
        float2 pA, pB;
        pA.x = to_tf32f(S[fn][0] * invA); pA.y = to_tf32f(S[fn][1] * invA);
        pB.x = to_tf32f(S[fn][2] * invB); pB.y = to_tf32f(S[fn][3] * invB);
        *(float2*)&ps[rA * PS_LD + c] = pA;
        *(float2*)&ps[rB * PS_LD + c] = pB;
    }
    __syncwarp();   // each warp reads only its own P rows below

    // ---- PV via tf32 mma: O[rows16fm x 80] = P[16 x 64] * vT^T ----
    const uint32_t aP = qs_b + (uint32_t)((fm * 16 + (lane & 15)) * (PS_LD * 4)
                                          + (lane >> 4) * 16);
    uint32_t bV[5];
    #pragma unroll
    for (int p = 0; p < 5; p++)
        bV[p] = vT_b + (uint32_t)((p * 16 + (lane & 7) + ((lane >> 4) << 3)) * (VT_LD * 4)
                                  + ((lane >> 3) & 1) * 16);

    float O[10][4];
    #pragma unroll
    for (int i = 0; i < 10; i++)
        #pragma unroll
        for (int j = 0; j < 4; j++) O[i][j] = 0.f;

    #pragma unroll
    for (int k8 = 0; k8 < 8; k8++) {
        uint32_t a0, a1, a2, a3;
        LDSM_X4(a0, a1, a2, a3, aP + k8 * 32);
        #pragma unroll
        for (int p = 0; p < 5; p++) {
            uint32_t b0, b1, b2, b3;
            LDSM_X4(b0, b1, b2, b3, bV[p] + k8 * 32);
            MMA_TF32(O[2 * p],     a0, a1, a2, a3, b0, b1);
            MMA_TF32(O[2 * p + 1], a0, a1, a2, a3, b2, b3);
        }
    }

    // ---- output (tf32-rounded fp32 for GEMM2) ----
    #pragma unroll
    for (int fn = 0; fn < 10; fn++) {
        const int c = fn * 8 + cb;
        const size_t oA = (size_t)(w * WS_WIN + rA) * D_HID + h * HD_DIM + c;
        const size_t oB = (size_t)(w * WS_WIN + rB) * D_HID + h * HD_DIM + c;
        float2 a2, b2;
        a2.x = to_tf32f(O[fn][0]); a2.y = to_tf32f(O[fn][1]);
        b2.x = to_tf32f(O[fn][2]); b2.y = to_tf32f(O[fn][3]);
        *(float2*)&out_t[oA] = a2;
        *(float2*)&out_t[oB] = b2;
    }
}

// ---------------------------------------------------------------------------
// launch
// ---------------------------------------------------------------------------
extern "C" void kernel_launch(void* const* d_in, const int* in_sizes, int n_in,
                              void* d_out, int out_size)
{
    (void)in_sizes; (void)n_in; (void)out_size;
    const float* hidden = (const float*)d_in[0];
    const float* masks  = (const float*)d_in[1];
    const float* cosv   = (const float*)d_in[2];
    const float* sinv   = (const float*)d_in[3];
    const float* qkv_w  = (const float*)d_in[4];
    const float* qkv_b  = (const float*)d_in[5];
    const float* proj_w = (const float*)d_in[6];
    const float* proj_b = (const float*)d_in[7];
    float* out = (float*)d_out;

    float *qkv_buf, *hid_t, *wqkv_t, *wproj_t, *attn_t;
    cudaGetSymbolAddress((void**)&qkv_buf, g_qkv);
    cudaGetSymbolAddress((void**)&hid_t, g_hid_t);
    cudaGetSymbolAddress((void**)&wqkv_t, g_wqkv_t);
    cudaGetSymbolAddress((void**)&wproj_t, g_wproj_t);
    cudaGetSymbolAddress((void**)&attn_t, g_attn_t);

    // 0) fp32 -> tf32 prepass for GEMM1 inputs only
    to_tf32_pre<<<(N4_PRE + 255) / 256, 256>>>(hidden, hid_t, qkv_w, wqkv_t);

    // 1) QKV projection (mma.sync tf32): [S,1280] x [3840,1280]^T + b
    {
        cudaFuncSetAttribute(gemm_tf32, cudaFuncAttributeMaxDynamicSharedMemorySize, GEMM_SMEM);
        dim3 grid(QKV_N / BN, S_LEN / BM);
        gemm_tf32<<<grid, 256, GEMM_SMEM>>>(hid_t, wqkv_t, qkv_b, qkv_buf, QKV_N);
    }

    // 2) windowed attention (+ piggybacked wproj tf32 conversion)
    {
        cudaFuncSetAttribute(attn_kernel, cudaFuncAttributeMaxDynamicSharedMemorySize, ATTN_SMEM);
        attn_kernel<<<ATTN_BLOCKS + CONV_BLOCKS, 128, ATTN_SMEM>>>(
            qkv_buf, masks, cosv, sinv, attn_t, proj_w, wproj_t);
    }

    // 3) output projection (mma.sync tf32): [S,1280] x [1280,1280]^T + b
    {
        dim3 grid(D_HID / BN, S_LEN / BM);
        gemm_tf32<<<grid, 256, GEMM_SMEM>>>(attn_t, wproj_t, proj_b, out, D_HID);
    }
}